// round 14
// baseline (speedup 1.0000x reference)
#include <cuda_runtime.h>
#include <math.h>
#include <stdint.h>

#define NB 64
#define MB 32
#define NM 2048         // worst-case node rows
#define FEATD 256
#define POSD 6
#define DD 262
#define DP 288          // padded feature dim (x4, 9 K-slabs of 32)
#define MSGD 128
#define NCLSD 7
#define G3 786
#define MGN 914
#define MGLD 916
#define GXN 786
#define GXLD 788
#define BIGN 1442       // merged [A(262)+2 | B(262)+2 | msg(128) | gh(786)]
#define BIGLD 1444

// ---------------- scratch (zero-initialized device globals) ----------------
__device__ float g_h   [NM*DP];      // fp32 h state, FULL row layout (valid rows only written)
__device__ float g_hqc [NM*DP];      // tf32-quantized h, COMPACTED rows (pad cols stay 0)
__device__ float g_big [NM*BIGLD];   // merged AB|msg|gh (round 0), compacted rows
__device__ float g_Wbig[BIGLD*DP];   // quantized [W1a|0|W1b|0|msg_w|gru_w_hh|0]
__device__ float g_bbig[BIGLD];      // [b1|0|0|msg_b|gru_b_hh|0]
__device__ float g_Wih [G3*MSGD];    // quantized gru_w_ih
__device__ float g_mg  [NM*MGLD];    // [msg | gh] (round 1), compacted rows
__device__ float g_att [NB*MB*MB];
__device__ float g_mv  [NM*MSGD];    // quantized, compacted rows
__device__ float g_gx  [NM*GXLD];    // compacted rows
__device__ float g_w2p [264];        // padded link_w2 (66 float4 exactly)
__device__ float g_cb  [2];          // [invalid-pair constant, b2]
__device__ int   g_start[NB];        // per-batch compacted row start
__device__ int   g_cnt [2];          // [cnt, cnt_pad64]
__device__ int   g_rowinfo[NM];      // compacted idx -> full row id (b*32+m)

__device__ __forceinline__ float sigmoidf(float x) {
    return 1.0f / (1.0f + expf(-x));
}
__device__ __forceinline__ uint32_t f2tf(float v) {
    uint32_t r; asm("cvt.rna.tf32.f32 %0, %1;" : "=r"(r) : "f"(v)); return r;
}
__device__ __forceinline__ float f2tff(float v) {
    return __uint_as_float(f2tf(v));
}
__device__ __forceinline__ void mma_tf32(float* c, const uint32_t* a, const uint32_t* b) {
    asm volatile(
        "mma.sync.aligned.m16n8k8.row.col.f32.tf32.tf32.f32 "
        "{%0,%1,%2,%3}, {%4,%5,%6,%7}, {%8,%9}, {%0,%1,%2,%3};\n"
        : "+f"(c[0]), "+f"(c[1]), "+f"(c[2]), "+f"(c[3])
        : "r"(a[0]), "r"(a[1]), "r"(a[2]), "r"(a[3]), "r"(b[0]), "r"(b[1]));
}

// ---------------- count: prefix-sum num_rec -> start/cnt ----------------
__global__ void count_kernel(const int* __restrict__ num_rec) {
    if (threadIdx.x == 0) {
        int acc = 0;
        for (int b = 0; b < NB; b++) { g_start[b] = acc; acc += num_rec[b]; }
        g_cnt[0] = acc;
        g_cnt[1] = (acc + 63) & ~63;
    }
}

// ---------------- prep: h (valid rows) + hqc (compacted) + weights + att constants ----------------
__global__ void prep_kernel(const float* __restrict__ feat,
                            const float* __restrict__ pos,
                            const int*   __restrict__ num_rec,
                            const float* __restrict__ link_w1,
                            const float* __restrict__ link_b1,
                            const float* __restrict__ link_w2,
                            const float* __restrict__ link_b2,
                            const float* __restrict__ msg_w,
                            const float* __restrict__ msg_b,
                            const float* __restrict__ gru_w_ih,
                            const float* __restrict__ gru_w_hh,
                            const float* __restrict__ gru_b_hh) {
    int idx = blockIdx.x * blockDim.x + threadIdx.x;
    int stride = gridDim.x * blockDim.x;
    // h (valid rows only) + hqc compacted
    for (int i = idx; i < NM * DD; i += stride) {
        int row = i / DD, c = i % DD;
        int b = row >> 5, m = row & 31;
        if (m < num_rec[b]) {
            float v = (c < FEATD) ? feat[row * FEATD + c] : pos[row * POSD + (c - FEATD)];
            g_h[row * DP + c] = v;
            int ci = g_start[b] + m;
            g_hqc[(size_t)ci * DP + c] = f2tff(v);
            if (c == 0) g_rowinfo[ci] = row;
        }
    }
    // Wbig rows 0..261 = W1a ; 264..525 = W1b
    for (int i = idx; i < 524 * DD; i += stride) {
        int n = i / DD, k = i % DD;
        int dr = (n < DD) ? n : (n + 2);
        float v = (n < DD) ? link_w1[n * 524 + k] : link_w1[(n - DD) * 524 + DD + k];
        g_Wbig[dr * DP + k] = f2tff(v);
    }
    // Wbig rows 528..655 = msg_w ; 656..1441 = gru_w_hh
    for (int i = idx; i < MGN * DD; i += stride) {
        int n = i / DD, k = i % DD;
        float v = (n < MSGD) ? msg_w[n * DD + k] : gru_w_hh[(n - MSGD) * DD + k];
        g_Wbig[(528 + n) * DP + k] = f2tff(v);
    }
    for (int i = idx; i < G3 * MSGD; i += stride) g_Wih[i] = f2tff(gru_w_ih[i]);
    for (int i = idx; i < DD; i += stride) {
        g_bbig[i] = link_b1[i];
        g_w2p[i] = link_w2[i];
    }
    for (int i = idx; i < MGN; i += stride)
        g_bbig[528 + i] = (i < MSGD) ? msg_b[i] : gru_b_hh[i - MSGD];
    // attention constants
    if (blockIdx.x == 0 && threadIdx.x < 32) {
        int lane = threadIdx.x;
        float s = 0.0f;
        for (int d = lane; d < DD; d += 32)
            s += fmaxf(link_b1[d], 0.0f) * link_w2[d];
        #pragma unroll
        for (int o = 16; o > 0; o >>= 1) s += __shfl_xor_sync(0xffffffffu, s, o);
        if (lane == 0) {
            g_cb[0] = sigmoidf(s + link_b2[0]);
            g_cb[1] = link_b2[0];
        }
    }
}

// ---------------- TF32 TC GEMM over COMPACTED rows (M = g_cnt[1]) ----------------
#define BK 32
#define SLD 36
#define A_STG (64 * SLD)
#define W_STG (128 * SLD)
__global__ __launch_bounds__(256) void gemm_tc_kernel(
        const float* __restrict__ A, int lda,
        const float* __restrict__ W, int ldw,
        const float* __restrict__ bias,
        float* __restrict__ C, int ldc, int N, int K) {
    int m0 = blockIdx.y * 64;
    if (m0 >= g_cnt[1]) return;       // compacted-M early exit
    __shared__ uint32_t As[2 * A_STG];
    __shared__ uint32_t Ws[2 * W_STG];

    int tid = threadIdx.x;
    int warp = tid >> 5, lane = tid & 31;
    int gid = lane >> 2, tig = lane & 3;
    int wm = (warp >> 2) * 32;
    int wn = (warp & 3) * 32;
    int n0 = blockIdx.x * 128;

    int arow = tid >> 2, akc = (tid & 3) * 8;
    int wrow = tid >> 1, wkc = (tid & 1) * 16;
    int wng = n0 + wrow;
    int wclamp = (wng < N) ? wng : (N - 1);
    const uint4* ap = (const uint4*)(A + (size_t)(m0 + arow) * lda + akc);
    const uint4* wp = (const uint4*)(W + (size_t)wclamp * ldw + wkc);

    float acc[2][4][4];
    #pragma unroll
    for (int i = 0; i < 2; i++)
        #pragma unroll
        for (int j = 0; j < 4; j++)
            #pragma unroll
            for (int q = 0; q < 4; q++) acc[i][j][q] = 0.0f;

    int nk = K / BK;
    uint4 va0, va1, vw0, vw1, vw2, vw3;

    va0 = ap[0]; va1 = ap[1];
    vw0 = wp[0]; vw1 = wp[1]; vw2 = wp[2]; vw3 = wp[3];
    {
        uint32_t* ad = As + arow * SLD + akc;
        *(uint4*)(ad)     = va0;
        *(uint4*)(ad + 4) = va1;
        uint32_t* wd = Ws + wrow * SLD + wkc;
        *(uint4*)(wd)      = vw0;
        *(uint4*)(wd + 4)  = vw1;
        *(uint4*)(wd + 8)  = vw2;
        *(uint4*)(wd + 12) = vw3;
    }
    __syncthreads();

    int buf = 0;
    for (int it = 0; it < nk; it++) {
        if (it + 1 < nk) {
            int o = (it + 1) * 8;
            va0 = ap[o]; va1 = ap[o + 1];
            vw0 = wp[o]; vw1 = wp[o + 1]; vw2 = wp[o + 2]; vw3 = wp[o + 3];
        }

        const uint32_t* Ab = As + buf * A_STG;
        const uint32_t* Wb = Ws + buf * W_STG;
        #pragma unroll
        for (int ks = 0; ks < 4; ks++) {
            int kb = ks * 8;
            uint32_t af[2][4], bf[4][2];
            #pragma unroll
            for (int mf = 0; mf < 2; mf++) {
                const uint32_t* pa = Ab + (wm + mf * 16 + gid) * SLD + kb + tig;
                af[mf][0] = pa[0];
                af[mf][1] = pa[8 * SLD];
                af[mf][2] = pa[4];
                af[mf][3] = pa[8 * SLD + 4];
            }
            #pragma unroll
            for (int nf = 0; nf < 4; nf++) {
                const uint32_t* pb = Wb + (wn + nf * 8 + gid) * SLD + kb + tig;
                bf[nf][0] = pb[0];
                bf[nf][1] = pb[4];
            }
            #pragma unroll
            for (int mf = 0; mf < 2; mf++)
                #pragma unroll
                for (int nf = 0; nf < 4; nf++)
                    mma_tf32(acc[mf][nf], af[mf], bf[nf]);
        }

        if (it + 1 < nk) {
            int nb = buf ^ 1;
            uint32_t* ad = As + nb * A_STG + arow * SLD + akc;
            *(uint4*)(ad)     = va0;
            *(uint4*)(ad + 4) = va1;
            uint32_t* wd = Ws + nb * W_STG + wrow * SLD + wkc;
            *(uint4*)(wd)      = vw0;
            *(uint4*)(wd + 4)  = vw1;
            *(uint4*)(wd + 8)  = vw2;
            *(uint4*)(wd + 12) = vw3;
            __syncthreads();
            buf = nb;
        }
    }

    #pragma unroll
    for (int nf = 0; nf < 4; nf++) {
        int col = n0 + wn + nf * 8 + tig * 2;
        if (col >= N) continue;
        float2 bv = *(const float2*)(bias + col);
        #pragma unroll
        for (int mf = 0; mf < 2; mf++) {
            int r0 = m0 + wm + mf * 16 + gid;
            float2 v0 = make_float2(acc[mf][nf][0] + bv.x, acc[mf][nf][1] + bv.y);
            float2 v1 = make_float2(acc[mf][nf][2] + bv.x, acc[mf][nf][3] + bv.y);
            *(float2*)(C + (size_t)r0 * ldc + col) = v0;
            *(float2*)(C + (size_t)(r0 + 8) * ldc + col) = v1;
        }
    }
}

// ---------------- attention: warp per (b,n) row; A+w2 in registers; loop w ----------------
__global__ void att_kernel(const int* __restrict__ num_rec,
                           float* __restrict__ att_out) {
    int gw = (blockIdx.x * blockDim.x + threadIdx.x) >> 5;   // (b*32+n)
    int lane = threadIdx.x & 31;
    if (gw >= NB * MB) return;
    int b = gw >> 5, n = gw & 31;
    int nr = num_rec[b];
    float cb = g_cb[0], b2 = g_cb[1];
    float* o1 = g_att + (size_t)gw * MB;
    float* o2 = att_out + (size_t)gw * MB;

    if (n >= nr) {                    // whole row constant
        o1[lane] = cb;
        o2[lane] = cb;
        return;
    }

    int sb = g_start[b];
    const float4 z = make_float4(0.f, 0.f, 0.f, 0.f);
    const float4* wv = (const float4*)g_w2p;                  // exactly 66 float4
    const float4* ra = (const float4*)(g_big + (size_t)(sb + n) * BIGLD);
    float4 a0 = ra[lane], a1 = ra[lane + 32];
    float4 a2 = (lane < 2) ? ra[lane + 64] : z;
    float4 q0 = wv[lane], q1 = wv[lane + 32];
    float4 q2 = (lane < 2) ? wv[lane + 64] : z;

    int w = 0;
    for (; w + 2 <= nr; w += 2) {
        const float4* rb0 = (const float4*)(g_big + (size_t)(sb + w) * BIGLD + 264);
        const float4* rb1 = (const float4*)(g_big + (size_t)(sb + w + 1) * BIGLD + 264);
        float4 b00 = rb0[lane], b01 = rb0[lane + 32];
        float4 b02 = (lane < 2) ? rb0[lane + 64] : z;
        float4 b10 = rb1[lane], b11 = rb1[lane + 32];
        float4 b12 = (lane < 2) ? rb1[lane + 64] : z;
        float s0 = 0.f, s1 = 0.f;
        s0 = fmaf(fmaxf(a0.x + b00.x, 0.f), q0.x, s0); s0 = fmaf(fmaxf(a0.y + b00.y, 0.f), q0.y, s0);
        s0 = fmaf(fmaxf(a0.z + b00.z, 0.f), q0.z, s0); s0 = fmaf(fmaxf(a0.w + b00.w, 0.f), q0.w, s0);
        s0 = fmaf(fmaxf(a1.x + b01.x, 0.f), q1.x, s0); s0 = fmaf(fmaxf(a1.y + b01.y, 0.f), q1.y, s0);
        s0 = fmaf(fmaxf(a1.z + b01.z, 0.f), q1.z, s0); s0 = fmaf(fmaxf(a1.w + b01.w, 0.f), q1.w, s0);
        s0 = fmaf(fmaxf(a2.x + b02.x, 0.f), q2.x, s0); s0 = fmaf(fmaxf(a2.y + b02.y, 0.f), q2.y, s0);
        s0 = fmaf(fmaxf(a2.z + b02.z, 0.f), q2.z, s0); s0 = fmaf(fmaxf(a2.w + b02.w, 0.f), q2.w, s0);
        s1 = fmaf(fmaxf(a0.x + b10.x, 0.f), q0.x, s1); s1 = fmaf(fmaxf(a0.y + b10.y, 0.f), q0.y, s1);
        s1 = fmaf(fmaxf(a0.z + b10.z, 0.f), q0.z, s1); s1 = fmaf(fmaxf(a0.w + b10.w, 0.f), q0.w, s1);
        s1 = fmaf(fmaxf(a1.x + b11.x, 0.f), q1.x, s1); s1 = fmaf(fmaxf(a1.y + b11.y, 0.f), q1.y, s1);
        s1 = fmaf(fmaxf(a1.z + b11.z, 0.f), q1.z, s1); s1 = fmaf(fmaxf(a1.w + b11.w, 0.f), q1.w, s1);
        s1 = fmaf(fmaxf(a2.x + b12.x, 0.f), q2.x, s1); s1 = fmaf(fmaxf(a2.y + b12.y, 0.f), q2.y, s1);
        s1 = fmaf(fmaxf(a2.z + b12.z, 0.f), q2.z, s1); s1 = fmaf(fmaxf(a2.w + b12.w, 0.f), q2.w, s1);
        #pragma unroll
        for (int o = 16; o > 0; o >>= 1) {
            s0 += __shfl_xor_sync(0xffffffffu, s0, o);
            s1 += __shfl_xor_sync(0xffffffffu, s1, o);
        }
        if (lane == 0) {
            float r0v = sigmoidf(s0 + b2);
            float r1v = sigmoidf(s1 + b2);
            o1[w] = r0v;     o1[w + 1] = r1v;
            o2[w] = r0v;     o2[w + 1] = r1v;
        }
    }
    if (w < nr) {                      // odd tail
        const float4* rb0 = (const float4*)(g_big + (size_t)(sb + w) * BIGLD + 264);
        float4 b00 = rb0[lane], b01 = rb0[lane + 32];
        float4 b02 = (lane < 2) ? rb0[lane + 64] : z;
        float s0 = 0.f;
        s0 = fmaf(fmaxf(a0.x + b00.x, 0.f), q0.x, s0); s0 = fmaf(fmaxf(a0.y + b00.y, 0.f), q0.y, s0);
        s0 = fmaf(fmaxf(a0.z + b00.z, 0.f), q0.z, s0); s0 = fmaf(fmaxf(a0.w + b00.w, 0.f), q0.w, s0);
        s0 = fmaf(fmaxf(a1.x + b01.x, 0.f), q1.x, s0); s0 = fmaf(fmaxf(a1.y + b01.y, 0.f), q1.y, s0);
        s0 = fmaf(fmaxf(a1.z + b01.z, 0.f), q1.z, s0); s0 = fmaf(fmaxf(a1.w + b01.w, 0.f), q1.w, s0);
        s0 = fmaf(fmaxf(a2.x + b02.x, 0.f), q2.x, s0); s0 = fmaf(fmaxf(a2.y + b02.y, 0.f), q2.y, s0);
        s0 = fmaf(fmaxf(a2.z + b02.z, 0.f), q2.z, s0); s0 = fmaf(fmaxf(a2.w + b02.w, 0.f), q2.w, s0);
        #pragma unroll
        for (int o = 16; o > 0; o >>= 1) s0 += __shfl_xor_sync(0xffffffffu, s0, o);
        if (lane == 0) {
            float r0v = sigmoidf(s0 + b2);
            o1[w] = r0v;  o2[w] = r0v;
        }
    }
    if (lane >= nr) {                  // invalid-sender tail (constant)
        o1[lane] = cb;
        o2[lane] = cb;
    }
}

// ---------------- mv: warp per compacted row; shuffle att; float4 msg ----------------
__global__ void mv_kernel(const int* __restrict__ num_rec,
                          const float* __restrict__ msgbase, int ld) {
    int gw = (blockIdx.x * blockDim.x + threadIdx.x) >> 5;   // compacted row
    int lane = threadIdx.x & 31;
    if (gw >= g_cnt[0]) return;
    int info = g_rowinfo[gw];
    int b = info >> 5;
    int nr = num_rec[b];
    int sb = g_start[b];

    float a_l = g_att[(size_t)info * MB + lane];

    const float4* mb = (const float4*)msgbase;
    int ld4 = ld >> 2;

    float4 c0 = make_float4(0.f,0.f,0.f,0.f);
    float4 c1 = make_float4(0.f,0.f,0.f,0.f);
    float4 c2 = make_float4(0.f,0.f,0.f,0.f);
    float4 c3 = make_float4(0.f,0.f,0.f,0.f);

    int w = 0;
    for (; w + 4 <= nr; w += 4) {
        float a0 = __shfl_sync(0xffffffffu, a_l, w);
        float a1 = __shfl_sync(0xffffffffu, a_l, w + 1);
        float a2 = __shfl_sync(0xffffffffu, a_l, w + 2);
        float a3 = __shfl_sync(0xffffffffu, a_l, w + 3);
        float4 m0 = mb[(size_t)(sb + w    ) * ld4 + lane];
        float4 m1 = mb[(size_t)(sb + w + 1) * ld4 + lane];
        float4 m2 = mb[(size_t)(sb + w + 2) * ld4 + lane];
        float4 m3 = mb[(size_t)(sb + w + 3) * ld4 + lane];
        c0.x = fmaf(a0, m0.x, c0.x); c0.y = fmaf(a0, m0.y, c0.y);
        c0.z = fmaf(a0, m0.z, c0.z); c0.w = fmaf(a0, m0.w, c0.w);
        c1.x = fmaf(a1, m1.x, c1.x); c1.y = fmaf(a1, m1.y, c1.y);
        c1.z = fmaf(a1, m1.z, c1.z); c1.w = fmaf(a1, m1.w, c1.w);
        c2.x = fmaf(a2, m2.x, c2.x); c2.y = fmaf(a2, m2.y, c2.y);
        c2.z = fmaf(a2, m2.z, c2.z); c2.w = fmaf(a2, m2.w, c2.w);
        c3.x = fmaf(a3, m3.x, c3.x); c3.y = fmaf(a3, m3.y, c3.y);
        c3.z = fmaf(a3, m3.z, c3.z); c3.w = fmaf(a3, m3.w, c3.w);
    }
    for (; w < nr; w++) {
        float a0 = __shfl_sync(0xffffffffu, a_l, w);
        float4 m0 = mb[(size_t)(sb + w) * ld4 + lane];
        c0.x = fmaf(a0, m0.x, c0.x); c0.y = fmaf(a0, m0.y, c0.y);
        c0.z = fmaf(a0, m0.z, c0.z); c0.w = fmaf(a0, m0.w, c0.w);
    }
    float4 s;
    s.x = (c0.x + c1.x) + (c2.x + c3.x);
    s.y = (c0.y + c1.y) + (c2.y + c3.y);
    s.z = (c0.z + c1.z) + (c2.z + c3.z);
    s.w = (c0.w + c1.w) + (c2.w + c3.w);
    float4 q = make_float4(f2tff(s.x), f2tff(s.y), f2tff(s.z), f2tff(s.w));
    *(float4*)(g_mv + (size_t)gw * MSGD + lane * 4) = q;
}

// ---------------- GRU combine over compacted rows; scatter h; rebuild hqc ----------------
__global__ void gru_kernel(const float* __restrict__ ghbase, int ld, int off) {
    int idx = blockIdx.x * blockDim.x + threadIdx.x;
    if (idx >= NM * 131) return;
    int cidx = idx / 131;
    if (cidx >= g_cnt[0]) return;
    int d = (idx % 131) * 2;
    int row = g_rowinfo[cidx];
    const float* gx = g_gx + (size_t)cidx * GXLD + d;
    const float* gh = ghbase + (size_t)cidx * ld + off + d;
    float2 xr = *(const float2*)(gx);
    float2 xz = *(const float2*)(gx + 262);
    float2 xn = *(const float2*)(gx + 524);
    float2 hr = *(const float2*)(gh);
    float2 hz = *(const float2*)(gh + 262);
    float2 hn = *(const float2*)(gh + 524);
    float2 hv = *(const float2*)(g_h + (size_t)row * DP + d);
    float rx = sigmoidf(xr.x + hr.x), ry = sigmoidf(xr.y + hr.y);
    float zx = sigmoidf(xz.x + hz.x), zy = sigmoidf(xz.y + hz.y);
    float cx = tanhf(xn.x + rx * hn.x), cy = tanhf(xn.y + ry * hn.y);
    float ox = (1.0f - zx) * cx + zx * hv.x;
    float oy = (1.0f - zy) * cy + zy * hv.y;
    *(float2*)(g_h   + (size_t)row  * DP + d) = make_float2(ox, oy);
    *(float2*)(g_hqc + (size_t)cidx * DP + d) = make_float2(f2tff(ox), f2tff(oy));
}

// ---------------- fused readout (full h layout; output masked) ----------------
#define SH_LD 266
#define ST_LD 133
__global__ void readout_kernel(const float* __restrict__ ro_w1,
                               const float* __restrict__ ro_b1,
                               const float* __restrict__ ro_w2,
                               const float* __restrict__ ro_b2,
                               const int* __restrict__ num_rec,
                               float* __restrict__ out) {
    extern __shared__ float s[];
    float* sh = s;                    // 32 x 266
    float* st = s + MB * SH_LD;       // 32 x 133
    int b = blockIdx.x;
    int tid = threadIdx.x;            // 0..511
    int lane = tid & 31, wid = tid >> 5;
    int nr = num_rec[b];

    for (int i = tid; i < MB * 131; i += 512) {
        int r = i / 131, d = (i % 131) * 2;
        float2 v = (r < nr) ? *(const float2*)(g_h + (size_t)(b * MB + r) * DP + d)
                            : make_float2(0.f, 0.f);
        *(float2*)(sh + r * SH_LD + d) = v;
    }
    __syncthreads();

    int r = lane;
    #pragma unroll 1
    for (int j = 0; j < 8; j++) {
        int k = wid * 8 + j;
        const float2* wrow = (const float2*)(ro_w1 + (size_t)k * DD);
        const float2* hrow = (const float2*)(sh + r * SH_LD);
        float acc = 0.0f;
        #pragma unroll 4
        for (int i = 0; i < DD / 2; i++) {
            float2 ww = __ldg(wrow + i);
            float2 hh = hrow[i];
            acc = fmaf(hh.x, ww.x, acc);
            acc = fmaf(hh.y, ww.y, acc);
        }
        st[r * ST_LD + k] = fmaxf(acc + ro_b1[k], 0.0f);
    }
    __syncthreads();

    if (tid < MB * NCLSD) {
        int rr = tid / NCLSD, c = tid % NCLSD;
        float acc = ro_b2[c];
        #pragma unroll 4
        for (int k = 0; k < MSGD; k++)
            acc = fmaf(st[rr * ST_LD + k], __ldg(ro_w2 + (size_t)c * MSGD + k), acc);
        out[(size_t)(b * MB + rr) * NCLSD + c] = (rr < nr) ? acc : 0.0f;
    }
}

// ---------------- host launcher ----------------
static void launch_gemm(const float* A, int lda, const float* W, int ldw,
                        const float* bias, float* C, int ldc, int N, int K) {
    dim3 grid((N + 127) / 128, NM / 64);
    gemm_tc_kernel<<<grid, 256>>>(A, lda, W, ldw, bias, C, ldc, N, K);
}

extern "C" void kernel_launch(void* const* d_in, const int* in_sizes, int n_in,
                              void* d_out, int out_size) {
    const float* feat    = (const float*)d_in[0];
    const float* pos     = (const float*)d_in[1];
    const int*   num_rec = (const int*)  d_in[2];
    const float* link_w1 = (const float*)d_in[3];
    const float* link_b1 = (const float*)d_in[4];
    const float* link_w2 = (const float*)d_in[5];
    const float* link_b2 = (const float*)d_in[6];
    const float* msg_w   = (const float*)d_in[7];
    const float* msg_b   = (const float*)d_in[8];
    const float* gru_w_ih= (const float*)d_in[9];
    const float* gru_w_hh= (const float*)d_in[10];
    const float* gru_b_ih= (const float*)d_in[11];
    const float* gru_b_hh= (const float*)d_in[12];
    const float* ro_w1   = (const float*)d_in[13];
    const float* ro_b1   = (const float*)d_in[14];
    const float* ro_w2   = (const float*)d_in[15];
    const float* ro_b2   = (const float*)d_in[16];
    float* out = (float*)d_out;           // [pred (64*32*7) | attmat (64*32*32)]

    float *p_hqc, *p_big, *p_Wbig, *p_bbig, *p_Wih, *p_mg, *p_mv, *p_gx;
    cudaGetSymbolAddress((void**)&p_hqc,  g_hqc);
    cudaGetSymbolAddress((void**)&p_big,  g_big);
    cudaGetSymbolAddress((void**)&p_Wbig, g_Wbig);
    cudaGetSymbolAddress((void**)&p_bbig, g_bbig);
    cudaGetSymbolAddress((void**)&p_Wih,  g_Wih);
    cudaGetSymbolAddress((void**)&p_mg,   g_mg);
    cudaGetSymbolAddress((void**)&p_mv,   g_mv);
    cudaGetSymbolAddress((void**)&p_gx,   g_gx);

    static const size_t RO_SMEM = (size_t)(MB * SH_LD + MB * ST_LD) * sizeof(float);
    cudaFuncSetAttribute(readout_kernel, cudaFuncAttributeMaxDynamicSharedMemorySize,
                         (int)RO_SMEM);

    // 1) count + prep
    count_kernel<<<1, 32>>>(num_rec);
    prep_kernel<<<296, 256>>>(feat, pos, num_rec, link_w1, link_b1, link_w2, link_b2,
                              msg_w, msg_b, gru_w_ih, gru_w_hh, gru_b_hh);

    // 2) merged GEMM over compacted rows: [AB | msg | gh0] = hqc @ Wbig^T + bbig
    launch_gemm(p_hqc, DP, p_Wbig, DP, p_bbig, p_big, BIGLD, BIGN, DP);

    // 3) attention (warp per (b,n) row)
    att_kernel<<<(NB * MB * 32 + 255) / 256, 256>>>(num_rec, out + NM * NCLSD);

    // 4) round 0
    mv_kernel<<<NM / 4, 128>>>(num_rec, p_big + 528, BIGLD);
    launch_gemm(p_mv, MSGD, p_Wih, MSGD, gru_b_ih, p_gx, GXLD, GXN, MSGD);
    gru_kernel<<<(NM * 131 + 255) / 256, 256>>>(p_big, BIGLD, 656);

    // 5) round 1
    launch_gemm(p_hqc, DP, p_Wbig + 528 * DP, DP, p_bbig + 528, p_mg, MGLD, MGN, DP);
    mv_kernel<<<NM / 4, 128>>>(num_rec, p_mg, MGLD);
    launch_gemm(p_mv, MSGD, p_Wih, MSGD, gru_b_ih, p_gx, GXLD, GXN, MSGD);
    gru_kernel<<<(NM * 131 + 255) / 256, 256>>>(p_mg, MGLD, 128);

    // 6) fused readout
    readout_kernel<<<NB, 512, RO_SMEM>>>(ro_w1, ro_b1, ro_w2, ro_b2, num_rec, out);

    (void)in_sizes; (void)n_in; (void)out_size;
}

// round 15
// speedup vs baseline: 1.1082x; 1.1082x over previous
#include <cuda_runtime.h>
#include <math.h>
#include <stdint.h>

#define NB 64
#define MB 32
#define NM 2048         // worst-case node rows
#define FEATD 256
#define POSD 6
#define DD 262
#define DP 288          // padded feature dim (x4, 9 K-slabs of 32)
#define MSGD 128
#define NCLSD 7
#define G3 786
#define MGN 914
#define MGLD 916
#define GXN 786
#define GXLD 788
#define BIGN 1442       // merged [A(262)+2 | B(262)+2 | msg(128) | gh(786)]
#define BIGLD 1444

// ---------------- scratch (zero-initialized device globals) ----------------
__device__ float g_h   [NM*DP];      // fp32 h state, FULL row layout (valid rows only written)
__device__ float g_hqc [NM*DP];      // tf32-quantized h, COMPACTED rows (pad cols stay 0)
__device__ float g_big [NM*BIGLD];   // merged AB|msg|gh (round 0), compacted rows
__device__ float g_Wbig[BIGLD*DP];   // quantized [W1a|0|W1b|0|msg_w|gru_w_hh|0]
__device__ float g_bbig[BIGLD];      // [b1|0|0|msg_b|gru_b_hh|0]
__device__ float g_Wih [G3*MSGD];    // quantized gru_w_ih
__device__ float g_mg  [NM*MGLD];    // [msg | gh] (round 1), compacted rows
__device__ float g_att [NB*MB*MB];
__device__ float g_mv  [NM*MSGD];    // quantized, compacted rows
__device__ float g_gx  [NM*GXLD];    // compacted rows
__device__ float g_w2p [264];        // padded link_w2
__device__ float g_cb  [2];          // [invalid-pair constant, b2]
__device__ int   g_start[NB];        // per-batch compacted row start
__device__ int   g_cnt [2];          // [cnt, cnt_pad64]
__device__ int   g_rowinfo[NM];      // compacted idx -> full row id (b*32+m)

__device__ __forceinline__ float sigmoidf(float x) {
    return 1.0f / (1.0f + expf(-x));
}
__device__ __forceinline__ uint32_t f2tf(float v) {
    uint32_t r; asm("cvt.rna.tf32.f32 %0, %1;" : "=r"(r) : "f"(v)); return r;
}
__device__ __forceinline__ float f2tff(float v) {
    return __uint_as_float(f2tf(v));
}
__device__ __forceinline__ void mma_tf32(float* c, const uint32_t* a, const uint32_t* b) {
    asm volatile(
        "mma.sync.aligned.m16n8k8.row.col.f32.tf32.tf32.f32 "
        "{%0,%1,%2,%3}, {%4,%5,%6,%7}, {%8,%9}, {%0,%1,%2,%3};\n"
        : "+f"(c[0]), "+f"(c[1]), "+f"(c[2]), "+f"(c[3])
        : "r"(a[0]), "r"(a[1]), "r"(a[2]), "r"(a[3]), "r"(b[0]), "r"(b[1]));
}

// ---------------- count: prefix-sum num_rec -> start/cnt ----------------
__global__ void count_kernel(const int* __restrict__ num_rec) {
    if (threadIdx.x == 0) {
        int acc = 0;
        for (int b = 0; b < NB; b++) { g_start[b] = acc; acc += num_rec[b]; }
        g_cnt[0] = acc;
        g_cnt[1] = (acc + 63) & ~63;
    }
}

// ---------------- prep: h (valid rows) + hqc (compacted) + weights + att constants ----------------
__global__ void prep_kernel(const float* __restrict__ feat,
                            const float* __restrict__ pos,
                            const int*   __restrict__ num_rec,
                            const float* __restrict__ link_w1,
                            const float* __restrict__ link_b1,
                            const float* __restrict__ link_w2,
                            const float* __restrict__ link_b2,
                            const float* __restrict__ msg_w,
                            const float* __restrict__ msg_b,
                            const float* __restrict__ gru_w_ih,
                            const float* __restrict__ gru_w_hh,
                            const float* __restrict__ gru_b_hh) {
    int idx = blockIdx.x * blockDim.x + threadIdx.x;
    int stride = gridDim.x * blockDim.x;
    // h (valid rows only) + hqc compacted
    for (int i = idx; i < NM * DD; i += stride) {
        int row = i / DD, c = i % DD;
        int b = row >> 5, m = row & 31;
        if (m < num_rec[b]) {
            float v = (c < FEATD) ? feat[row * FEATD + c] : pos[row * POSD + (c - FEATD)];
            g_h[row * DP + c] = v;
            int ci = g_start[b] + m;
            g_hqc[(size_t)ci * DP + c] = f2tff(v);
            if (c == 0) g_rowinfo[ci] = row;
        }
    }
    // Wbig rows 0..261 = W1a ; 264..525 = W1b
    for (int i = idx; i < 524 * DD; i += stride) {
        int n = i / DD, k = i % DD;
        int dr = (n < DD) ? n : (n + 2);
        float v = (n < DD) ? link_w1[n * 524 + k] : link_w1[(n - DD) * 524 + DD + k];
        g_Wbig[dr * DP + k] = f2tff(v);
    }
    // Wbig rows 528..655 = msg_w ; 656..1441 = gru_w_hh
    for (int i = idx; i < MGN * DD; i += stride) {
        int n = i / DD, k = i % DD;
        float v = (n < MSGD) ? msg_w[n * DD + k] : gru_w_hh[(n - MSGD) * DD + k];
        g_Wbig[(528 + n) * DP + k] = f2tff(v);
    }
    for (int i = idx; i < G3 * MSGD; i += stride) g_Wih[i] = f2tff(gru_w_ih[i]);
    for (int i = idx; i < DD; i += stride) {
        g_bbig[i] = link_b1[i];
        g_w2p[i] = link_w2[i];
    }
    for (int i = idx; i < MGN; i += stride)
        g_bbig[528 + i] = (i < MSGD) ? msg_b[i] : gru_b_hh[i - MSGD];
    // attention constants
    if (blockIdx.x == 0 && threadIdx.x < 32) {
        int lane = threadIdx.x;
        float s = 0.0f;
        for (int d = lane; d < DD; d += 32)
            s += fmaxf(link_b1[d], 0.0f) * link_w2[d];
        #pragma unroll
        for (int o = 16; o > 0; o >>= 1) s += __shfl_xor_sync(0xffffffffu, s, o);
        if (lane == 0) {
            g_cb[0] = sigmoidf(s + link_b2[0]);
            g_cb[1] = link_b2[0];
        }
    }
}

// ---------------- TF32 TC GEMM over COMPACTED rows (M = g_cnt[1]) ----------------
#define BK 32
#define SLD 36
#define A_STG (64 * SLD)
#define W_STG (128 * SLD)
__global__ __launch_bounds__(256) void gemm_tc_kernel(
        const float* __restrict__ A, int lda,
        const float* __restrict__ W, int ldw,
        const float* __restrict__ bias,
        float* __restrict__ C, int ldc, int N, int K) {
    int m0 = blockIdx.y * 64;
    if (m0 >= g_cnt[1]) return;       // compacted-M early exit
    __shared__ uint32_t As[2 * A_STG];
    __shared__ uint32_t Ws[2 * W_STG];

    int tid = threadIdx.x;
    int warp = tid >> 5, lane = tid & 31;
    int gid = lane >> 2, tig = lane & 3;
    int wm = (warp >> 2) * 32;
    int wn = (warp & 3) * 32;
    int n0 = blockIdx.x * 128;

    int arow = tid >> 2, akc = (tid & 3) * 8;
    int wrow = tid >> 1, wkc = (tid & 1) * 16;
    int wng = n0 + wrow;
    int wclamp = (wng < N) ? wng : (N - 1);
    const uint4* ap = (const uint4*)(A + (size_t)(m0 + arow) * lda + akc);
    const uint4* wp = (const uint4*)(W + (size_t)wclamp * ldw + wkc);

    float acc[2][4][4];
    #pragma unroll
    for (int i = 0; i < 2; i++)
        #pragma unroll
        for (int j = 0; j < 4; j++)
            #pragma unroll
            for (int q = 0; q < 4; q++) acc[i][j][q] = 0.0f;

    int nk = K / BK;
    uint4 va0, va1, vw0, vw1, vw2, vw3;

    va0 = ap[0]; va1 = ap[1];
    vw0 = wp[0]; vw1 = wp[1]; vw2 = wp[2]; vw3 = wp[3];
    {
        uint32_t* ad = As + arow * SLD + akc;
        *(uint4*)(ad)     = va0;
        *(uint4*)(ad + 4) = va1;
        uint32_t* wd = Ws + wrow * SLD + wkc;
        *(uint4*)(wd)      = vw0;
        *(uint4*)(wd + 4)  = vw1;
        *(uint4*)(wd + 8)  = vw2;
        *(uint4*)(wd + 12) = vw3;
    }
    __syncthreads();

    int buf = 0;
    for (int it = 0; it < nk; it++) {
        if (it + 1 < nk) {
            int o = (it + 1) * 8;
            va0 = ap[o]; va1 = ap[o + 1];
            vw0 = wp[o]; vw1 = wp[o + 1]; vw2 = wp[o + 2]; vw3 = wp[o + 3];
        }

        const uint32_t* Ab = As + buf * A_STG;
        const uint32_t* Wb = Ws + buf * W_STG;
        #pragma unroll
        for (int ks = 0; ks < 4; ks++) {
            int kb = ks * 8;
            uint32_t af[2][4], bf[4][2];
            #pragma unroll
            for (int mf = 0; mf < 2; mf++) {
                const uint32_t* pa = Ab + (wm + mf * 16 + gid) * SLD + kb + tig;
                af[mf][0] = pa[0];
                af[mf][1] = pa[8 * SLD];
                af[mf][2] = pa[4];
                af[mf][3] = pa[8 * SLD + 4];
            }
            #pragma unroll
            for (int nf = 0; nf < 4; nf++) {
                const uint32_t* pb = Wb + (wn + nf * 8 + gid) * SLD + kb + tig;
                bf[nf][0] = pb[0];
                bf[nf][1] = pb[4];
            }
            #pragma unroll
            for (int mf = 0; mf < 2; mf++)
                #pragma unroll
                for (int nf = 0; nf < 4; nf++)
                    mma_tf32(acc[mf][nf], af[mf], bf[nf]);
        }

        if (it + 1 < nk) {
            int nb = buf ^ 1;
            uint32_t* ad = As + nb * A_STG + arow * SLD + akc;
            *(uint4*)(ad)     = va0;
            *(uint4*)(ad + 4) = va1;
            uint32_t* wd = Ws + nb * W_STG + wrow * SLD + wkc;
            *(uint4*)(wd)      = vw0;
            *(uint4*)(wd + 4)  = vw1;
            *(uint4*)(wd + 8)  = vw2;
            *(uint4*)(wd + 12) = vw3;
            __syncthreads();
            buf = nb;
        }
    }

    #pragma unroll
    for (int nf = 0; nf < 4; nf++) {
        int col = n0 + wn + nf * 8 + tig * 2;
        if (col >= N) continue;
        float2 bv = *(const float2*)(bias + col);
        #pragma unroll
        for (int mf = 0; mf < 2; mf++) {
            int r0 = m0 + wm + mf * 16 + gid;
            float2 v0 = make_float2(acc[mf][nf][0] + bv.x, acc[mf][nf][1] + bv.y);
            float2 v1 = make_float2(acc[mf][nf][2] + bv.x, acc[mf][nf][3] + bv.y);
            *(float2*)(C + (size_t)r0 * ldc + col) = v0;
            *(float2*)(C + (size_t)(r0 + 8) * ldc + col) = v1;
        }
    }
}

// ---------------- attention: 2 pairs per warp; compacted AB rows ----------------
__global__ void att_kernel(const int* __restrict__ num_rec,
                           float* __restrict__ att_out) {
    int gw = (blockIdx.x * blockDim.x + threadIdx.x) >> 5;
    int lane = threadIdx.x & 31;
    if (gw >= NB * MB * 16) return;
    int b = gw >> 9;
    int rem = gw & 511;
    int n = rem >> 4, w0 = (rem & 15) * 2;
    int nr = num_rec[b];
    float cb = g_cb[0];
    float b2 = g_cb[1];
    int oidx = (b * MB + n) * MB + w0;

    bool v0 = (n < nr) && (w0 < nr);
    bool v1 = (n < nr) && (w0 + 1 < nr);
    if (!v0) {                        // v1 <= v0, so both invalid
        if (lane == 0) {
            g_att[oidx] = cb;     g_att[oidx + 1] = cb;
            att_out[oidx] = cb;   att_out[oidx + 1] = cb;
        }
        return;
    }

    int sb = g_start[b];
    const float4* ra  = (const float4*)(g_big + (size_t)(sb + n) * BIGLD);       // A+b1
    const float4* rb0 = (const float4*)(g_big + (size_t)(sb + w0) * BIGLD + 264);
    const float4* rb1 = (const float4*)(g_big + (size_t)(sb + w0 + 1) * BIGLD + 264);
    const float4* wv  = (const float4*)g_w2p;

    float s0 = 0.0f, s1 = 0.0f;
    if (v1) {
        #pragma unroll 1
        for (int i = lane; i < 66; i += 32) {
            float4 a = ra[i], ww = wv[i];
            float4 b0 = rb0[i], b1v = rb1[i];
            s0 = fmaf(fmaxf(a.x + b0.x, 0.0f), ww.x, s0);
            s0 = fmaf(fmaxf(a.y + b0.y, 0.0f), ww.y, s0);
            s0 = fmaf(fmaxf(a.z + b0.z, 0.0f), ww.z, s0);
            s0 = fmaf(fmaxf(a.w + b0.w, 0.0f), ww.w, s0);
            s1 = fmaf(fmaxf(a.x + b1v.x, 0.0f), ww.x, s1);
            s1 = fmaf(fmaxf(a.y + b1v.y, 0.0f), ww.y, s1);
            s1 = fmaf(fmaxf(a.z + b1v.z, 0.0f), ww.z, s1);
            s1 = fmaf(fmaxf(a.w + b1v.w, 0.0f), ww.w, s1);
        }
    } else {
        #pragma unroll 1
        for (int i = lane; i < 66; i += 32) {
            float4 a = ra[i], ww = wv[i], b0 = rb0[i];
            s0 = fmaf(fmaxf(a.x + b0.x, 0.0f), ww.x, s0);
            s0 = fmaf(fmaxf(a.y + b0.y, 0.0f), ww.y, s0);
            s0 = fmaf(fmaxf(a.z + b0.z, 0.0f), ww.z, s0);
            s0 = fmaf(fmaxf(a.w + b0.w, 0.0f), ww.w, s0);
        }
    }
    #pragma unroll
    for (int o = 16; o > 0; o >>= 1) {
        s0 += __shfl_xor_sync(0xffffffffu, s0, o);
        s1 += __shfl_xor_sync(0xffffffffu, s1, o);
    }
    if (lane == 0) {
        float a0 = sigmoidf(s0 + b2);
        float a1 = v1 ? sigmoidf(s1 + b2) : cb;
        g_att[oidx] = a0;     g_att[oidx + 1] = a1;
        att_out[oidx] = a0;   att_out[oidx + 1] = a1;
    }
}

// ---------------- mv: warp per compacted row; shuffle att; float4 msg ----------------
__global__ void mv_kernel(const int* __restrict__ num_rec,
                          const float* __restrict__ msgbase, int ld) {
    int gw = (blockIdx.x * blockDim.x + threadIdx.x) >> 5;   // compacted row
    int lane = threadIdx.x & 31;
    if (gw >= g_cnt[0]) return;
    int info = g_rowinfo[gw];
    int b = info >> 5;
    int nr = num_rec[b];
    int sb = g_start[b];

    float a_l = g_att[(size_t)info * MB + lane];

    const float4* mb = (const float4*)msgbase;
    int ld4 = ld >> 2;

    float4 c0 = make_float4(0.f,0.f,0.f,0.f);
    float4 c1 = make_float4(0.f,0.f,0.f,0.f);
    float4 c2 = make_float4(0.f,0.f,0.f,0.f);
    float4 c3 = make_float4(0.f,0.f,0.f,0.f);

    int w = 0;
    for (; w + 4 <= nr; w += 4) {
        float a0 = __shfl_sync(0xffffffffu, a_l, w);
        float a1 = __shfl_sync(0xffffffffu, a_l, w + 1);
        float a2 = __shfl_sync(0xffffffffu, a_l, w + 2);
        float a3 = __shfl_sync(0xffffffffu, a_l, w + 3);
        float4 m0 = mb[(size_t)(sb + w    ) * ld4 + lane];
        float4 m1 = mb[(size_t)(sb + w + 1) * ld4 + lane];
        float4 m2 = mb[(size_t)(sb + w + 2) * ld4 + lane];
        float4 m3 = mb[(size_t)(sb + w + 3) * ld4 + lane];
        c0.x = fmaf(a0, m0.x, c0.x); c0.y = fmaf(a0, m0.y, c0.y);
        c0.z = fmaf(a0, m0.z, c0.z); c0.w = fmaf(a0, m0.w, c0.w);
        c1.x = fmaf(a1, m1.x, c1.x); c1.y = fmaf(a1, m1.y, c1.y);
        c1.z = fmaf(a1, m1.z, c1.z); c1.w = fmaf(a1, m1.w, c1.w);
        c2.x = fmaf(a2, m2.x, c2.x); c2.y = fmaf(a2, m2.y, c2.y);
        c2.z = fmaf(a2, m2.z, c2.z); c2.w = fmaf(a2, m2.w, c2.w);
        c3.x = fmaf(a3, m3.x, c3.x); c3.y = fmaf(a3, m3.y, c3.y);
        c3.z = fmaf(a3, m3.z, c3.z); c3.w = fmaf(a3, m3.w, c3.w);
    }
    for (; w < nr; w++) {
        float a0 = __shfl_sync(0xffffffffu, a_l, w);
        float4 m0 = mb[(size_t)(sb + w) * ld4 + lane];
        c0.x = fmaf(a0, m0.x, c0.x); c0.y = fmaf(a0, m0.y, c0.y);
        c0.z = fmaf(a0, m0.z, c0.z); c0.w = fmaf(a0, m0.w, c0.w);
    }
    float4 s;
    s.x = (c0.x + c1.x) + (c2.x + c3.x);
    s.y = (c0.y + c1.y) + (c2.y + c3.y);
    s.z = (c0.z + c1.z) + (c2.z + c3.z);
    s.w = (c0.w + c1.w) + (c2.w + c3.w);
    float4 q = make_float4(f2tff(s.x), f2tff(s.y), f2tff(s.z), f2tff(s.w));
    *(float4*)(g_mv + (size_t)gw * MSGD + lane * 4) = q;
}

// ---------------- GRU combine over compacted rows; scatter h; rebuild hqc ----------------
__global__ void gru_kernel(const float* __restrict__ ghbase, int ld, int off) {
    int idx = blockIdx.x * blockDim.x + threadIdx.x;
    if (idx >= NM * 131) return;
    int cidx = idx / 131;
    if (cidx >= g_cnt[0]) return;
    int d = (idx % 131) * 2;
    int row = g_rowinfo[cidx];
    const float* gx = g_gx + (size_t)cidx * GXLD + d;
    const float* gh = ghbase + (size_t)cidx * ld + off + d;
    float2 xr = *(const float2*)(gx);
    float2 xz = *(const float2*)(gx + 262);
    float2 xn = *(const float2*)(gx + 524);
    float2 hr = *(const float2*)(gh);
    float2 hz = *(const float2*)(gh + 262);
    float2 hn = *(const float2*)(gh + 524);
    float2 hv = *(const float2*)(g_h + (size_t)row * DP + d);
    float rx = sigmoidf(xr.x + hr.x), ry = sigmoidf(xr.y + hr.y);
    float zx = sigmoidf(xz.x + hz.x), zy = sigmoidf(xz.y + hz.y);
    float cx = tanhf(xn.x + rx * hn.x), cy = tanhf(xn.y + ry * hn.y);
    float ox = (1.0f - zx) * cx + zx * hv.x;
    float oy = (1.0f - zy) * cy + zy * hv.y;
    *(float2*)(g_h   + (size_t)row  * DP + d) = make_float2(ox, oy);
    *(float2*)(g_hqc + (size_t)cidx * DP + d) = make_float2(f2tff(ox), f2tff(oy));
}

// ---------------- fused readout (full h layout; output masked) ----------------
#define SH_LD 266
#define ST_LD 133
__global__ void readout_kernel(const float* __restrict__ ro_w1,
                               const float* __restrict__ ro_b1,
                               const float* __restrict__ ro_w2,
                               const float* __restrict__ ro_b2,
                               const int* __restrict__ num_rec,
                               float* __restrict__ out) {
    extern __shared__ float s[];
    float* sh = s;                    // 32 x 266
    float* st = s + MB * SH_LD;       // 32 x 133
    int b = blockIdx.x;
    int tid = threadIdx.x;            // 0..511
    int lane = tid & 31, wid = tid >> 5;
    int nr = num_rec[b];

    for (int i = tid; i < MB * 131; i += 512) {
        int r = i / 131, d = (i % 131) * 2;
        float2 v = (r < nr) ? *(const float2*)(g_h + (size_t)(b * MB + r) * DP + d)
                            : make_float2(0.f, 0.f);
        *(float2*)(sh + r * SH_LD + d) = v;
    }
    __syncthreads();

    int r = lane;
    #pragma unroll 1
    for (int j = 0; j < 8; j++) {
        int k = wid * 8 + j;
        const float2* wrow = (const float2*)(ro_w1 + (size_t)k * DD);
        const float2* hrow = (const float2*)(sh + r * SH_LD);
        float acc = 0.0f;
        #pragma unroll 4
        for (int i = 0; i < DD / 2; i++) {
            float2 ww = __ldg(wrow + i);
            float2 hh = hrow[i];
            acc = fmaf(hh.x, ww.x, acc);
            acc = fmaf(hh.y, ww.y, acc);
        }
        st[r * ST_LD + k] = fmaxf(acc + ro_b1[k], 0.0f);
    }
    __syncthreads();

    if (tid < MB * NCLSD) {
        int rr = tid / NCLSD, c = tid % NCLSD;
        float acc = ro_b2[c];
        #pragma unroll 4
        for (int k = 0; k < MSGD; k++)
            acc = fmaf(st[rr * ST_LD + k], __ldg(ro_w2 + (size_t)c * MSGD + k), acc);
        out[(size_t)(b * MB + rr) * NCLSD + c] = (rr < nr) ? acc : 0.0f;
    }
}

// ---------------- host launcher ----------------
static void launch_gemm(const float* A, int lda, const float* W, int ldw,
                        const float* bias, float* C, int ldc, int N, int K) {
    dim3 grid((N + 127) / 128, NM / 64);
    gemm_tc_kernel<<<grid, 256>>>(A, lda, W, ldw, bias, C, ldc, N, K);
}

extern "C" void kernel_launch(void* const* d_in, const int* in_sizes, int n_in,
                              void* d_out, int out_size) {
    const float* feat    = (const float*)d_in[0];
    const float* pos     = (const float*)d_in[1];
    const int*   num_rec = (const int*)  d_in[2];
    const float* link_w1 = (const float*)d_in[3];
    const float* link_b1 = (const float*)d_in[4];
    const float* link_w2 = (const float*)d_in[5];
    const float* link_b2 = (const float*)d_in[6];
    const float* msg_w   = (const float*)d_in[7];
    const float* msg_b   = (const float*)d_in[8];
    const float* gru_w_ih= (const float*)d_in[9];
    const float* gru_w_hh= (const float*)d_in[10];
    const float* gru_b_ih= (const float*)d_in[11];
    const float* gru_b_hh= (const float*)d_in[12];
    const float* ro_w1   = (const float*)d_in[13];
    const float* ro_b1   = (const float*)d_in[14];
    const float* ro_w2   = (const float*)d_in[15];
    const float* ro_b2   = (const float*)d_in[16];
    float* out = (float*)d_out;           // [pred (64*32*7) | attmat (64*32*32)]

    float *p_hqc, *p_big, *p_Wbig, *p_bbig, *p_Wih, *p_mg, *p_mv, *p_gx;
    cudaGetSymbolAddress((void**)&p_hqc,  g_hqc);
    cudaGetSymbolAddress((void**)&p_big,  g_big);
    cudaGetSymbolAddress((void**)&p_Wbig, g_Wbig);
    cudaGetSymbolAddress((void**)&p_bbig, g_bbig);
    cudaGetSymbolAddress((void**)&p_Wih,  g_Wih);
    cudaGetSymbolAddress((void**)&p_mg,   g_mg);
    cudaGetSymbolAddress((void**)&p_mv,   g_mv);
    cudaGetSymbolAddress((void**)&p_gx,   g_gx);

    static const size_t RO_SMEM = (size_t)(MB * SH_LD + MB * ST_LD) * sizeof(float);
    cudaFuncSetAttribute(readout_kernel, cudaFuncAttributeMaxDynamicSharedMemorySize,
                         (int)RO_SMEM);

    // 1) count + prep
    count_kernel<<<1, 32>>>(num_rec);
    prep_kernel<<<296, 256>>>(feat, pos, num_rec, link_w1, link_b1, link_w2, link_b2,
                              msg_w, msg_b, gru_w_ih, gru_w_hh, gru_b_hh);

    // 2) merged GEMM over compacted rows: [AB | msg | gh0] = hqc @ Wbig^T + bbig
    launch_gemm(p_hqc, DP, p_Wbig, DP, p_bbig, p_big, BIGLD, BIGN, DP);

    // 3) attention (2 pairs/warp, constant fast path, compacted AB rows)
    {
        int warps = NB * MB * 16;
        att_kernel<<<(warps * 32 + 255) / 256, 256>>>(num_rec, out + NM * NCLSD);
    }

    // 4) round 0
    mv_kernel<<<NM / 4, 128>>>(num_rec, p_big + 528, BIGLD);
    launch_gemm(p_mv, MSGD, p_Wih, MSGD, gru_b_ih, p_gx, GXLD, GXN, MSGD);
    gru_kernel<<<(NM * 131 + 255) / 256, 256>>>(p_big, BIGLD, 656);

    // 5) round 1
    launch_gemm(p_hqc, DP, p_Wbig + 528 * DP, DP, p_bbig + 528, p_mg, MGLD, MGN, DP);
    mv_kernel<<<NM / 4, 128>>>(num_rec, p_mg, MGLD);
    launch_gemm(p_mv, MSGD, p_Wih, MSGD, gru_b_ih, p_gx, GXLD, GXN, MSGD);
    gru_kernel<<<(NM * 131 + 255) / 256, 256>>>(p_mg, MGLD, 128);

    // 6) fused readout
    readout_kernel<<<NB, 512, RO_SMEM>>>(ro_w1, ro_b1, ro_w2, ro_b2, num_rec, out);

    (void)in_sizes; (void)n_in; (void)out_size;
}